// round 15
// baseline (speedup 1.0000x reference)
#include <cuda_runtime.h>
#include <cuda_fp16.h>
#include <cstdint>

// out[m,n] = f32( f16( f32x[m,:] . (W[n,:]*scale) ) + f16(bias[n]) )
// Harness dtypes: x f32 [M,K], weight i32-or-i8 (probed) [N,K],
// scale f32 [N,K/128], bias f32 [N], out f32 [M,N]
// compute_103 virtual arch: NO tcgen05. Ceiling = legacy HMMA (~610 TF/s f32-acc).
// R9: R8 + LDSM/HMMA interleaved compute body + warp-parity ks rotation to
//     decorrelate smem-port bursts from tensor bursts (joint ~70% binding pair).

#define M_TOTAL 8192
#define N_TOTAL 11008
#define K_TOTAL 4096
#define GROUPSZ 128

#define BM 128
#define BN 256
#define BK 64
#define NSTAGE 4
#define NT (K_TOTAL / BK)   // 64
#define LDS_A 72            // 64 + 8 pad halves; conflict-free ldmatrix
#define LDS_B 72
#define THREADS 512

#define STRIDE_A ((uint32_t)(BM * LDS_A * 2))            // 18432 B / stage
#define STRIDE_B ((uint32_t)(BN * LDS_B * 2))            // 36864 B / stage
#define B_BASE   (NSTAGE * STRIDE_A)                     // 73728
#define SMEM_BYTES (B_BASE + NSTAGE * STRIDE_B)          // 221184 (fits 227KB)

// ---------------- scratch (f16 prepass outputs) ----------------
__device__ __half g_Ah[(size_t)M_TOTAL * K_TOTAL];   // 64 MB
__device__ __half g_Bh[(size_t)N_TOTAL * K_TOTAL];   // 88 MB
__device__ int    g_w_is_i32;

__device__ __forceinline__ uint32_t smem_u32(const void* p) {
    uint32_t a;
    asm("{ .reg .u64 t; cvta.to.shared.u64 t, %1; cvt.u32.u64 %0, t; }"
        : "=r"(a) : "l"(p));
    return a;
}

#define CP_ASYNC_16(dst_u32, src_ptr) \
    asm volatile("cp.async.cg.shared.global [%0], [%1], 16;" \
                 :: "r"(dst_u32), "l"(src_ptr) : "memory")
#define CP_COMMIT() asm volatile("cp.async.commit_group;" ::: "memory")
#define CP_WAIT(n)  asm volatile("cp.async.wait_group %0;" :: "n"(n) : "memory")

#define LDSM4(r0, r1, r2, r3, addr) \
    asm volatile("ldmatrix.sync.aligned.m8n8.x4.shared.b16 {%0,%1,%2,%3}, [%4];" \
                 : "=r"(r0), "=r"(r1), "=r"(r2), "=r"(r3) : "r"(addr))

#define HMMA(acc4, a4, b0, b1) \
    asm volatile( \
        "mma.sync.aligned.m16n8k16.row.col.f32.f16.f16.f32 " \
        "{%0,%1,%2,%3}, {%4,%5,%6,%7}, {%8,%9}, {%0,%1,%2,%3};" \
        : "+f"((acc4)[0]), "+f"((acc4)[1]), "+f"((acc4)[2]), "+f"((acc4)[3]) \
        : "r"((a4)[0]), "r"((a4)[1]), "r"((a4)[2]), "r"((a4)[3]), \
          "r"(b0), "r"(b1))

// ---------------- dtype probe ----------------
__global__ void probe_weight_kernel(const int8_t* __restrict__ w)
{
    if (threadIdx.x != 0 || blockIdx.x != 0) return;
    int votes = 0;
#pragma unroll
    for (int i = 0; i < 16; i++) {
        int8_t b0 = w[i * 4 + 0], b1 = w[i * 4 + 1], b2 = w[i * 4 + 2], b3 = w[i * 4 + 3];
        int8_t ext = (b0 < 0) ? (int8_t)-1 : (int8_t)0;
        if (b1 == ext && b2 == ext && b3 == ext) votes++;
    }
    g_w_is_i32 = (votes >= 14) ? 1 : 0;
}

// ---------------- prepass: x f32 -> f16 ----------------
__global__ __launch_bounds__(256) void convert_x_kernel(const float4* __restrict__ X)
{
    size_t i = (size_t)blockIdx.x * 256 + threadIdx.x;
    float4 a = X[2 * i], b = X[2 * i + 1];
    __half2 h0 = __floats2half2_rn(a.x, a.y);
    __half2 h1 = __floats2half2_rn(a.z, a.w);
    __half2 h2 = __floats2half2_rn(b.x, b.y);
    __half2 h3 = __floats2half2_rn(b.z, b.w);
    uint4 pk;
    pk.x = *(const uint32_t*)&h0; pk.y = *(const uint32_t*)&h1;
    pk.z = *(const uint32_t*)&h2; pk.w = *(const uint32_t*)&h3;
    reinterpret_cast<uint4*>(g_Ah)[i] = pk;
}

// ---------------- prepass: W dequant -> f16 ----------------
__global__ __launch_bounds__(256) void dequant_w_kernel(const void* __restrict__ Wv,
                                                        const float* __restrict__ S)
{
    size_t i = (size_t)blockIdx.x * 256 + threadIdx.x;
    size_t base = i * 8;
    int n = (int)(base / K_TOTAL);
    int k = (int)(base % K_TOTAL);
    float sc = S[(size_t)n * (K_TOTAL / GROUPSZ) + (k >> 7)];

    float f[8];
    if (g_w_is_i32) {
        const int4* W = reinterpret_cast<const int4*>(Wv);
        int4 v0 = W[i * 2], v1 = W[i * 2 + 1];
        f[0] = (float)v0.x; f[1] = (float)v0.y; f[2] = (float)v0.z; f[3] = (float)v0.w;
        f[4] = (float)v1.x; f[5] = (float)v1.y; f[6] = (float)v1.z; f[7] = (float)v1.w;
    } else {
        uint2 raw = reinterpret_cast<const uint2*>(Wv)[i];
        const int8_t* b = reinterpret_cast<const int8_t*>(&raw);
#pragma unroll
        for (int j = 0; j < 8; j++) f[j] = (float)b[j];
    }
    __half2 h0 = __floats2half2_rn(f[0] * sc, f[1] * sc);
    __half2 h1 = __floats2half2_rn(f[2] * sc, f[3] * sc);
    __half2 h2 = __floats2half2_rn(f[4] * sc, f[5] * sc);
    __half2 h3 = __floats2half2_rn(f[6] * sc, f[7] * sc);
    uint4 pk;
    pk.x = *(const uint32_t*)&h0; pk.y = *(const uint32_t*)&h1;
    pk.z = *(const uint32_t*)&h2; pk.w = *(const uint32_t*)&h3;
    reinterpret_cast<uint4*>(g_Bh)[i] = pk;
}

// ---------------- HMMA GEMM: 128x256, 512 thr, 4-stage, interleaved body -------
__global__ __launch_bounds__(THREADS, 1) void wq8_gemm_kernel(
    const float* __restrict__ BIAS,
    float* __restrict__ O)
{
    extern __shared__ __align__(16) __half smem[];
    const uint32_t sb = smem_u32(smem);

    const int tid  = threadIdx.x;
    const int lane = tid & 31;
    const int warp = tid >> 5;
    const int wm   = warp >> 3;   // 0..1 : 64-row slab
    const int wn   = warp & 7;    // 0..7 : 32-col slab

    const int m0 = blockIdx.y * BM;
    const int n0 = blockIdx.x * BN;

    float acc[4][4][4];
#pragma unroll
    for (int i = 0; i < 4; i++)
#pragma unroll
        for (int j = 0; j < 4; j++)
#pragma unroll
            for (int k = 0; k < 4; k++) acc[i][j][k] = 0.f;

    // ---- hoisted per-thread addressing ----
    const int l_row = tid >> 3;          // 0..63
    const int l_col = (tid & 7) * 8;     // half offset

    uint32_t sa_off[2], sbo_off[4];      // smem STS targets (stage 0)
    const __half* ga[2];
    const __half* gb[4];
#pragma unroll
    for (int i = 0; i < 2; i++) {
        int row = l_row + i * 64;
        sa_off[i] = sb + (uint32_t)(row * LDS_A + l_col) * 2;
        ga[i] = g_Ah + (size_t)(m0 + row) * K_TOTAL + l_col;
    }
#pragma unroll
    for (int i = 0; i < 4; i++) {
        int row = l_row + i * 64;
        sbo_off[i] = sb + B_BASE + (uint32_t)(row * LDS_B + l_col) * 2;
        gb[i] = g_Bh + (size_t)(n0 + row) * K_TOTAL + l_col;
    }

    // fragment LDSM base addresses (stage 0, ks 0)
    uint32_t a_off[4], b_off[2];
#pragma unroll
    for (int mi = 0; mi < 4; mi++)
        a_off[mi] = sb + (uint32_t)((wm * 64 + mi * 16 + (lane & 15)) * LDS_A +
                                    (lane >> 4) * 8) * 2;
    {
        int mm = lane >> 3;
#pragma unroll
        for (int bi = 0; bi < 2; bi++) {
            int nr = wn * 32 + bi * 16 + ((mm >> 1) << 3) + (lane & 7);
            b_off[bi] = sb + B_BASE +
                        (uint32_t)(nr * LDS_B + ((mm & 1) << 3)) * 2;
        }
    }

    // warp-parity ks rotation: odd warps walk ks = 2,3,0,1 (decorrelates
    // per-ks LDSM bursts across the 4 warps of each SMSP). Pure reorder of
    // fp32 accumulation, arithmetically equivalent set.
    uint32_t k4off[4];
    {
        int kr = (warp & 1) << 1;
#pragma unroll
        for (int ksi = 0; ksi < 4; ksi++)
            k4off[ksi] = (uint32_t)((((ksi + kr) & 3)) * 32);
    }

    auto issue_stage = [&](uint32_t offA, uint32_t offB) {
#pragma unroll
        for (int i = 0; i < 2; i++) {
            CP_ASYNC_16(sa_off[i] + offA, ga[i]);
            ga[i] += BK;
        }
#pragma unroll
        for (int i = 0; i < 4; i++) {
            CP_ASYNC_16(sbo_off[i] + offB, gb[i]);
            gb[i] += BK;
        }
    };

    // compute body: LDSM interleaved into the HMMA stream so the smem port
    // and tensor pipe overlap within a single warp (no extra registers).
    auto compute = [&](uint32_t offA, uint32_t offB) {
#pragma unroll
        for (int ksi = 0; ksi < 4; ksi++) {
            const uint32_t ko = k4off[ksi];
            uint32_t af[4][4];
            uint32_t bf[8];
            LDSM4(bf[0], bf[1], bf[2], bf[3], b_off[0] + offB + ko);
            LDSM4(bf[4], bf[5], bf[6], bf[7], b_off[1] + offB + ko);
            LDSM4(af[0][0], af[0][1], af[0][2], af[0][3], a_off[0] + offA + ko);
            LDSM4(af[1][0], af[1][1], af[1][2], af[1][3], a_off[1] + offA + ko);

            HMMA(acc[0][0], af[0], bf[0], bf[1]);
            HMMA(acc[0][1], af[0], bf[2], bf[3]);
            HMMA(acc[0][2], af[0], bf[4], bf[5]);
            HMMA(acc[0][3], af[0], bf[6], bf[7]);

            LDSM4(af[2][0], af[2][1], af[2][2], af[2][3], a_off[2] + offA + ko);

            HMMA(acc[1][0], af[1], bf[0], bf[1]);
            HMMA(acc[1][1], af[1], bf[2], bf[3]);
            HMMA(acc[1][2], af[1], bf[4], bf[5]);
            HMMA(acc[1][3], af[1], bf[6], bf[7]);

            LDSM4(af[3][0], af[3][1], af[3][2], af[3][3], a_off[3] + offA + ko);

            HMMA(acc[2][0], af[2], bf[0], bf[1]);
            HMMA(acc[2][1], af[2], bf[2], bf[3]);
            HMMA(acc[2][2], af[2], bf[4], bf[5]);
            HMMA(acc[2][3], af[2], bf[6], bf[7]);

            HMMA(acc[3][0], af[3], bf[0], bf[1]);
            HMMA(acc[3][1], af[3], bf[2], bf[3]);
            HMMA(acc[3][2], af[3], bf[4], bf[5]);
            HMMA(acc[3][3], af[3], bf[6], bf[7]);
        }
    };

    // prologue: fill 3 of 4 stages
    issue_stage(0 * STRIDE_A, 0 * STRIDE_B); CP_COMMIT();
    issue_stage(1 * STRIDE_A, 1 * STRIDE_B); CP_COMMIT();
    issue_stage(2 * STRIDE_A, 2 * STRIDE_B); CP_COMMIT();

    int next = 3;

#define BODY(CUR, NXT)                                                        \
    do {                                                                      \
        CP_WAIT(2);                                                           \
        __syncthreads();                                                      \
        compute((CUR) * STRIDE_A, (CUR) * STRIDE_B);                          \
        if (next < NT) {                                                      \
            issue_stage((NXT) * STRIDE_A, (NXT) * STRIDE_B);                  \
            next++;                                                           \
        }                                                                     \
        CP_COMMIT();                                                          \
    } while (0)

#pragma unroll 1
    for (int tu = 0; tu < NT / 4; tu++) {
        BODY(0, 3);
        BODY(1, 0);
        BODY(2, 1);
        BODY(3, 2);
    }
#undef BODY

    // ---- epilogue: f16(acc) + f16(bias), store f32 (matches reference rounding) ----
#pragma unroll
    for (int mi = 0; mi < 4; mi++) {
#pragma unroll
        for (int ni = 0; ni < 4; ni++) {
            int col = n0 + wn * 32 + ni * 8 + (lane & 3) * 2;
            float2 bf2 = *reinterpret_cast<const float2*>(BIAS + col);
            __half2 b2 = __floats2half2_rn(bf2.x, bf2.y);
            int r0 = m0 + wm * 64 + mi * 16 + (lane >> 2);

            __half2 v0 = __floats2half2_rn(acc[mi][ni][0], acc[mi][ni][1]);
            __half2 v1 = __floats2half2_rn(acc[mi][ni][2], acc[mi][ni][3]);
            float2 o0 = __half22float2(__hadd2(v0, b2));
            float2 o1 = __half22float2(__hadd2(v1, b2));
            *reinterpret_cast<float2*>(O + (size_t)r0 * N_TOTAL + col) = o0;
            *reinterpret_cast<float2*>(O + (size_t)(r0 + 8) * N_TOTAL + col) = o1;
        }
    }
}

extern "C" void kernel_launch(void* const* d_in, const int* in_sizes, int n_in,
                              void* d_out, int out_size)
{
    const float* x    = (const float*)d_in[0];
    const void*  w    = (const void*)d_in[1];
    const float* s    = (const float*)d_in[2];
    const float* bias = (const float*)d_in[3];
    float*       out  = (float*)d_out;

    cudaFuncSetAttribute(wq8_gemm_kernel,
                         cudaFuncAttributeMaxDynamicSharedMemorySize, SMEM_BYTES);

    probe_weight_kernel<<<1, 32>>>((const int8_t*)w);
    convert_x_kernel<<<(int)((size_t)M_TOTAL * K_TOTAL / 8 / 256), 256>>>(
        (const float4*)x);
    dequant_w_kernel<<<(int)((size_t)N_TOTAL * K_TOTAL / 8 / 256), 256>>>(w, s);

    dim3 grid(N_TOTAL / BN, M_TOTAL / BM);  // 43 x 64
    wq8_gemm_kernel<<<grid, THREADS, SMEM_BYTES>>>(bias, out);
}

// round 16
// speedup vs baseline: 1.0515x; 1.0515x over previous
#include <cuda_runtime.h>
#include <cuda_fp16.h>
#include <cstdint>

// out[m,n] = f32( f16( f32x[m,:] . (W[n,:]*scale) ) + f16(bias[n]) )
// Harness dtypes: x f32 [M,K], weight i32-or-i8 (probed) [N,K],
// scale f32 [N,K/128], bias f32 [N], out f32 [M,N]
// compute_103 virtual arch: NO tcgen05. Ceiling = legacy HMMA (~610 TF/s f32-acc).
// R10: R8 mechanics (hoisted addresses, compile-time stage offsets, unrolled
//      pipeline) on a 128x128 tile with 256 threads / 3 stages -> 2 CTAs per SM.
//      Second CTA fills the SM's issue slots during the peer's wait+sync window
//      (R8/R9 showed ~720 cyc/iter of exposed sync at occ=1; tensor pinned ~70%).

#define M_TOTAL 8192
#define N_TOTAL 11008
#define K_TOTAL 4096
#define GROUPSZ 128

#define BM 128
#define BN 128
#define BK 64
#define NSTAGE 3
#define NT (K_TOTAL / BK)   // 64
#define LDS_A 72            // 64 + 8 pad halves; conflict-free ldmatrix
#define LDS_B 72
#define THREADS 256

#define STRIDE_A ((uint32_t)(BM * LDS_A * 2))            // 18432 B / stage
#define STRIDE_B ((uint32_t)(BN * LDS_B * 2))            // 18432 B / stage
#define B_BASE   (NSTAGE * STRIDE_A)                     // 55296
#define SMEM_BYTES (B_BASE + NSTAGE * STRIDE_B)          // 110592 -> 2 CTAs/SM

// ---------------- scratch (f16 prepass outputs) ----------------
__device__ __half g_Ah[(size_t)M_TOTAL * K_TOTAL];   // 64 MB
__device__ __half g_Bh[(size_t)N_TOTAL * K_TOTAL];   // 88 MB
__device__ int    g_w_is_i32;

__device__ __forceinline__ uint32_t smem_u32(const void* p) {
    uint32_t a;
    asm("{ .reg .u64 t; cvta.to.shared.u64 t, %1; cvt.u32.u64 %0, t; }"
        : "=r"(a) : "l"(p));
    return a;
}

#define CP_ASYNC_16(dst_u32, src_ptr) \
    asm volatile("cp.async.cg.shared.global [%0], [%1], 16;" \
                 :: "r"(dst_u32), "l"(src_ptr) : "memory")
#define CP_COMMIT() asm volatile("cp.async.commit_group;" ::: "memory")
#define CP_WAIT(n)  asm volatile("cp.async.wait_group %0;" :: "n"(n) : "memory")

#define LDSM4(r0, r1, r2, r3, addr) \
    asm volatile("ldmatrix.sync.aligned.m8n8.x4.shared.b16 {%0,%1,%2,%3}, [%4];" \
                 : "=r"(r0), "=r"(r1), "=r"(r2), "=r"(r3) : "r"(addr))

#define HMMA(acc4, a4, b0, b1) \
    asm volatile( \
        "mma.sync.aligned.m16n8k16.row.col.f32.f16.f16.f32 " \
        "{%0,%1,%2,%3}, {%4,%5,%6,%7}, {%8,%9}, {%0,%1,%2,%3};" \
        : "+f"((acc4)[0]), "+f"((acc4)[1]), "+f"((acc4)[2]), "+f"((acc4)[3]) \
        : "r"((a4)[0]), "r"((a4)[1]), "r"((a4)[2]), "r"((a4)[3]), \
          "r"(b0), "r"(b1))

// ---------------- dtype probe ----------------
__global__ void probe_weight_kernel(const int8_t* __restrict__ w)
{
    if (threadIdx.x != 0 || blockIdx.x != 0) return;
    int votes = 0;
#pragma unroll
    for (int i = 0; i < 16; i++) {
        int8_t b0 = w[i * 4 + 0], b1 = w[i * 4 + 1], b2 = w[i * 4 + 2], b3 = w[i * 4 + 3];
        int8_t ext = (b0 < 0) ? (int8_t)-1 : (int8_t)0;
        if (b1 == ext && b2 == ext && b3 == ext) votes++;
    }
    g_w_is_i32 = (votes >= 14) ? 1 : 0;
}

// ---------------- prepass: x f32 -> f16 ----------------
__global__ __launch_bounds__(256) void convert_x_kernel(const float4* __restrict__ X)
{
    size_t i = (size_t)blockIdx.x * 256 + threadIdx.x;
    float4 a = X[2 * i], b = X[2 * i + 1];
    __half2 h0 = __floats2half2_rn(a.x, a.y);
    __half2 h1 = __floats2half2_rn(a.z, a.w);
    __half2 h2 = __floats2half2_rn(b.x, b.y);
    __half2 h3 = __floats2half2_rn(b.z, b.w);
    uint4 pk;
    pk.x = *(const uint32_t*)&h0; pk.y = *(const uint32_t*)&h1;
    pk.z = *(const uint32_t*)&h2; pk.w = *(const uint32_t*)&h3;
    reinterpret_cast<uint4*>(g_Ah)[i] = pk;
}

// ---------------- prepass: W dequant -> f16 ----------------
__global__ __launch_bounds__(256) void dequant_w_kernel(const void* __restrict__ Wv,
                                                        const float* __restrict__ S)
{
    size_t i = (size_t)blockIdx.x * 256 + threadIdx.x;
    size_t base = i * 8;
    int n = (int)(base / K_TOTAL);
    int k = (int)(base % K_TOTAL);
    float sc = S[(size_t)n * (K_TOTAL / GROUPSZ) + (k >> 7)];

    float f[8];
    if (g_w_is_i32) {
        const int4* W = reinterpret_cast<const int4*>(Wv);
        int4 v0 = W[i * 2], v1 = W[i * 2 + 1];
        f[0] = (float)v0.x; f[1] = (float)v0.y; f[2] = (float)v0.z; f[3] = (float)v0.w;
        f[4] = (float)v1.x; f[5] = (float)v1.y; f[6] = (float)v1.z; f[7] = (float)v1.w;
    } else {
        uint2 raw = reinterpret_cast<const uint2*>(Wv)[i];
        const int8_t* b = reinterpret_cast<const int8_t*>(&raw);
#pragma unroll
        for (int j = 0; j < 8; j++) f[j] = (float)b[j];
    }
    __half2 h0 = __floats2half2_rn(f[0] * sc, f[1] * sc);
    __half2 h1 = __floats2half2_rn(f[2] * sc, f[3] * sc);
    __half2 h2 = __floats2half2_rn(f[4] * sc, f[5] * sc);
    __half2 h3 = __floats2half2_rn(f[6] * sc, f[7] * sc);
    uint4 pk;
    pk.x = *(const uint32_t*)&h0; pk.y = *(const uint32_t*)&h1;
    pk.z = *(const uint32_t*)&h2; pk.w = *(const uint32_t*)&h3;
    reinterpret_cast<uint4*>(g_Bh)[i] = pk;
}

// ---------------- HMMA GEMM: 128x128, 256 thr, 3 stages, 2 CTAs/SM -------------
__global__ __launch_bounds__(THREADS, 2) void wq8_gemm_kernel(
    const float* __restrict__ BIAS,
    float* __restrict__ O)
{
    extern __shared__ __align__(16) __half smem[];
    const uint32_t sb = smem_u32(smem);

    const int tid  = threadIdx.x;
    const int lane = tid & 31;
    const int warp = tid >> 5;
    const int wm   = warp >> 2;   // 0..1 : 64-row slab
    const int wn   = warp & 3;    // 0..3 : 32-col slab

    const int m0 = blockIdx.y * BM;
    const int n0 = blockIdx.x * BN;

    float acc[4][4][4];
#pragma unroll
    for (int i = 0; i < 4; i++)
#pragma unroll
        for (int j = 0; j < 4; j++)
#pragma unroll
            for (int k = 0; k < 4; k++) acc[i][j][k] = 0.f;

    // ---- hoisted per-thread addressing ----
    // loader plan (256 thr): A 128x64 halves = 1024 chunks -> 4/thr; B same.
    const int l_row = tid >> 3;          // 0..31
    const int l_col = (tid & 7) * 8;     // half offset

    uint32_t sa_off[4], sbo_off[4];      // smem STS targets (stage 0)
    const __half* ga[4];                 // gmem cursors (advance BK per issue)
    const __half* gb[4];
#pragma unroll
    for (int i = 0; i < 4; i++) {
        int row = l_row + i * 32;
        sa_off[i]  = sb + (uint32_t)(row * LDS_A + l_col) * 2;
        ga[i] = g_Ah + (size_t)(m0 + row) * K_TOTAL + l_col;
        sbo_off[i] = sb + B_BASE + (uint32_t)(row * LDS_B + l_col) * 2;
        gb[i] = g_Bh + (size_t)(n0 + row) * K_TOTAL + l_col;
    }

    // fragment LDSM base addresses (stage 0, ks 0)
    uint32_t a_off[4], b_off[2];
#pragma unroll
    for (int mi = 0; mi < 4; mi++)
        a_off[mi] = sb + (uint32_t)((wm * 64 + mi * 16 + (lane & 15)) * LDS_A +
                                    (lane >> 4) * 8) * 2;
    {
        int mm = lane >> 3;
#pragma unroll
        for (int bi = 0; bi < 2; bi++) {
            int nr = wn * 32 + bi * 16 + ((mm >> 1) << 3) + (lane & 7);
            b_off[bi] = sb + B_BASE +
                        (uint32_t)(nr * LDS_B + ((mm & 1) << 3)) * 2;
        }
    }

    auto issue_stage = [&](uint32_t offA, uint32_t offB) {
#pragma unroll
        for (int i = 0; i < 4; i++) {
            CP_ASYNC_16(sa_off[i] + offA, ga[i]);
            ga[i] += BK;
        }
#pragma unroll
        for (int i = 0; i < 4; i++) {
            CP_ASYNC_16(sbo_off[i] + offB, gb[i]);
            gb[i] += BK;
        }
    };

    auto compute = [&](uint32_t offA, uint32_t offB) {
#pragma unroll
        for (int ks = 0; ks < 4; ks++) {
            const uint32_t ko = (uint32_t)(ks * 32);
            uint32_t af[4][4];
            uint32_t bf[8];
#pragma unroll
            for (int mi = 0; mi < 4; mi++)
                LDSM4(af[mi][0], af[mi][1], af[mi][2], af[mi][3],
                      a_off[mi] + offA + ko);
            LDSM4(bf[0], bf[1], bf[2], bf[3], b_off[0] + offB + ko);
            LDSM4(bf[4], bf[5], bf[6], bf[7], b_off[1] + offB + ko);
#pragma unroll
            for (int mi = 0; mi < 4; mi++)
#pragma unroll
                for (int ni = 0; ni < 4; ni++)
                    HMMA(acc[mi][ni], af[mi], bf[ni * 2], bf[ni * 2 + 1]);
        }
    };

    // prologue: fill 2 of 3 stages
    issue_stage(0 * STRIDE_A, 0 * STRIDE_B); CP_COMMIT();
    issue_stage(1 * STRIDE_A, 1 * STRIDE_B); CP_COMMIT();

    int next = 2;  // next k-block to issue

    // body: wait(<=1 pending) -> stage CUR resident; sync; compute(CUR);
    // issue k-block `next` into stage NXT; commit (empty in tail).
#define BODY(CUR, NXT)                                                        \
    do {                                                                      \
        CP_WAIT(1);                                                           \
        __syncthreads();                                                      \
        compute((CUR) * STRIDE_A, (CUR) * STRIDE_B);                          \
        if (next < NT) {                                                      \
            issue_stage((NXT) * STRIDE_A, (NXT) * STRIDE_B);                  \
            next++;                                                           \
        }                                                                     \
        CP_COMMIT();                                                          \
    } while (0)

    // 64 iterations = 21 * 3 + 1; stage of iter 63 is 0.
#pragma unroll 1
    for (int tu = 0; tu < NT / 3; tu++) {   // 21 unrolled triples (63 iters)
        BODY(0, 2);
        BODY(1, 0);
        BODY(2, 1);
    }
    BODY(0, 2);                             // iter 63 (issue guard is false)
#undef BODY

    // ---- epilogue: f16(acc) + f16(bias), store f32 (matches reference rounding) ----
#pragma unroll
    for (int mi = 0; mi < 4; mi++) {
#pragma unroll
        for (int ni = 0; ni < 4; ni++) {
            int col = n0 + wn * 32 + ni * 8 + (lane & 3) * 2;
            float2 bf2 = *reinterpret_cast<const float2*>(BIAS + col);
            __half2 b2 = __floats2half2_rn(bf2.x, bf2.y);
            int r0 = m0 + wm * 64 + mi * 16 + (lane >> 2);

            __half2 v0 = __floats2half2_rn(acc[mi][ni][0], acc[mi][ni][1]);
            __half2 v1 = __floats2half2_rn(acc[mi][ni][2], acc[mi][ni][3]);
            float2 o0 = __half22float2(__hadd2(v0, b2));
            float2 o1 = __half22float2(__hadd2(v1, b2));
            *reinterpret_cast<float2*>(O + (size_t)r0 * N_TOTAL + col) = o0;
            *reinterpret_cast<float2*>(O + (size_t)(r0 + 8) * N_TOTAL + col) = o1;
        }
    }
}

extern "C" void kernel_launch(void* const* d_in, const int* in_sizes, int n_in,
                              void* d_out, int out_size)
{
    const float* x    = (const float*)d_in[0];
    const void*  w    = (const void*)d_in[1];
    const float* s    = (const float*)d_in[2];
    const float* bias = (const float*)d_in[3];
    float*       out  = (float*)d_out;

    cudaFuncSetAttribute(wq8_gemm_kernel,
                         cudaFuncAttributeMaxDynamicSharedMemorySize, SMEM_BYTES);

    probe_weight_kernel<<<1, 32>>>((const int8_t*)w);
    convert_x_kernel<<<(int)((size_t)M_TOTAL * K_TOTAL / 8 / 256), 256>>>(
        (const float4*)x);
    dequant_w_kernel<<<(int)((size_t)N_TOTAL * K_TOTAL / 8 / 256), 256>>>(w, s);

    dim3 grid(N_TOTAL / BN, M_TOTAL / BM);  // 86 x 64
    wq8_gemm_kernel<<<grid, THREADS, SMEM_BYTES>>>(bias, out);
}

// round 17
// speedup vs baseline: 1.0530x; 1.0014x over previous
#include <cuda_runtime.h>
#include <cuda_fp16.h>
#include <cstdint>

// out[m,n] = f32( f16( f32x[m,:] . (W[n,:]*scale) ) + f16(bias[n]) )
// Harness dtypes: x f32 [M,K], weight i32-or-i8 (probed) [N,K],
// scale f32 [N,K/128], bias f32 [N], out f32 [M,N]
// compute_103 virtual arch: NO tcgen05. Ceiling = legacy HMMA (~610 TF/s f32-acc).
// R10: R8 mechanics (hoisted addresses, compile-time stage offsets, unrolled
//      pipeline) on a 128x128 tile with 256 threads / 3 stages -> 2 CTAs per SM.
//      Second CTA fills the SM's issue slots during the peer's wait+sync window
//      (R8/R9 showed ~720 cyc/iter of exposed sync at occ=1; tensor pinned ~70%).

#define M_TOTAL 8192
#define N_TOTAL 11008
#define K_TOTAL 4096
#define GROUPSZ 128

#define BM 128
#define BN 128
#define BK 64
#define NSTAGE 3
#define NT (K_TOTAL / BK)   // 64
#define LDS_A 72            // 64 + 8 pad halves; conflict-free ldmatrix
#define LDS_B 72
#define THREADS 256

#define STRIDE_A ((uint32_t)(BM * LDS_A * 2))            // 18432 B / stage
#define STRIDE_B ((uint32_t)(BN * LDS_B * 2))            // 18432 B / stage
#define B_BASE   (NSTAGE * STRIDE_A)                     // 55296
#define SMEM_BYTES (B_BASE + NSTAGE * STRIDE_B)          // 110592 -> 2 CTAs/SM

// ---------------- scratch (f16 prepass outputs) ----------------
__device__ __half g_Ah[(size_t)M_TOTAL * K_TOTAL];   // 64 MB
__device__ __half g_Bh[(size_t)N_TOTAL * K_TOTAL];   // 88 MB
__device__ int    g_w_is_i32;

__device__ __forceinline__ uint32_t smem_u32(const void* p) {
    uint32_t a;
    asm("{ .reg .u64 t; cvta.to.shared.u64 t, %1; cvt.u32.u64 %0, t; }"
        : "=r"(a) : "l"(p));
    return a;
}

#define CP_ASYNC_16(dst_u32, src_ptr) \
    asm volatile("cp.async.cg.shared.global [%0], [%1], 16;" \
                 :: "r"(dst_u32), "l"(src_ptr) : "memory")
#define CP_COMMIT() asm volatile("cp.async.commit_group;" ::: "memory")
#define CP_WAIT(n)  asm volatile("cp.async.wait_group %0;" :: "n"(n) : "memory")

#define LDSM4(r0, r1, r2, r3, addr) \
    asm volatile("ldmatrix.sync.aligned.m8n8.x4.shared.b16 {%0,%1,%2,%3}, [%4];" \
                 : "=r"(r0), "=r"(r1), "=r"(r2), "=r"(r3) : "r"(addr))

#define HMMA(acc4, a4, b0, b1) \
    asm volatile( \
        "mma.sync.aligned.m16n8k16.row.col.f32.f16.f16.f32 " \
        "{%0,%1,%2,%3}, {%4,%5,%6,%7}, {%8,%9}, {%0,%1,%2,%3};" \
        : "+f"((acc4)[0]), "+f"((acc4)[1]), "+f"((acc4)[2]), "+f"((acc4)[3]) \
        : "r"((a4)[0]), "r"((a4)[1]), "r"((a4)[2]), "r"((a4)[3]), \
          "r"(b0), "r"(b1))

// ---------------- dtype probe ----------------
__global__ void probe_weight_kernel(const int8_t* __restrict__ w)
{
    if (threadIdx.x != 0 || blockIdx.x != 0) return;
    int votes = 0;
#pragma unroll
    for (int i = 0; i < 16; i++) {
        int8_t b0 = w[i * 4 + 0], b1 = w[i * 4 + 1], b2 = w[i * 4 + 2], b3 = w[i * 4 + 3];
        int8_t ext = (b0 < 0) ? (int8_t)-1 : (int8_t)0;
        if (b1 == ext && b2 == ext && b3 == ext) votes++;
    }
    g_w_is_i32 = (votes >= 14) ? 1 : 0;
}

// ---------------- prepass: x f32 -> f16 ----------------
__global__ __launch_bounds__(256) void convert_x_kernel(const float4* __restrict__ X)
{
    size_t i = (size_t)blockIdx.x * 256 + threadIdx.x;
    float4 a = X[2 * i], b = X[2 * i + 1];
    __half2 h0 = __floats2half2_rn(a.x, a.y);
    __half2 h1 = __floats2half2_rn(a.z, a.w);
    __half2 h2 = __floats2half2_rn(b.x, b.y);
    __half2 h3 = __floats2half2_rn(b.z, b.w);
    uint4 pk;
    pk.x = *(const uint32_t*)&h0; pk.y = *(const uint32_t*)&h1;
    pk.z = *(const uint32_t*)&h2; pk.w = *(const uint32_t*)&h3;
    reinterpret_cast<uint4*>(g_Ah)[i] = pk;
}

// ---------------- prepass: W dequant -> f16 ----------------
__global__ __launch_bounds__(256) void dequant_w_kernel(const void* __restrict__ Wv,
                                                        const float* __restrict__ S)
{
    size_t i = (size_t)blockIdx.x * 256 + threadIdx.x;
    size_t base = i * 8;
    int n = (int)(base / K_TOTAL);
    int k = (int)(base % K_TOTAL);
    float sc = S[(size_t)n * (K_TOTAL / GROUPSZ) + (k >> 7)];

    float f[8];
    if (g_w_is_i32) {
        const int4* W = reinterpret_cast<const int4*>(Wv);
        int4 v0 = W[i * 2], v1 = W[i * 2 + 1];
        f[0] = (float)v0.x; f[1] = (float)v0.y; f[2] = (float)v0.z; f[3] = (float)v0.w;
        f[4] = (float)v1.x; f[5] = (float)v1.y; f[6] = (float)v1.z; f[7] = (float)v1.w;
    } else {
        uint2 raw = reinterpret_cast<const uint2*>(Wv)[i];
        const int8_t* b = reinterpret_cast<const int8_t*>(&raw);
#pragma unroll
        for (int j = 0; j < 8; j++) f[j] = (float)b[j];
    }
    __half2 h0 = __floats2half2_rn(f[0] * sc, f[1] * sc);
    __half2 h1 = __floats2half2_rn(f[2] * sc, f[3] * sc);
    __half2 h2 = __floats2half2_rn(f[4] * sc, f[5] * sc);
    __half2 h3 = __floats2half2_rn(f[6] * sc, f[7] * sc);
    uint4 pk;
    pk.x = *(const uint32_t*)&h0; pk.y = *(const uint32_t*)&h1;
    pk.z = *(const uint32_t*)&h2; pk.w = *(const uint32_t*)&h3;
    reinterpret_cast<uint4*>(g_Bh)[i] = pk;
}

// ---------------- HMMA GEMM: 128x128, 256 thr, 3 stages, 2 CTAs/SM -------------
__global__ __launch_bounds__(THREADS, 2) void wq8_gemm_kernel(
    const float* __restrict__ BIAS,
    float* __restrict__ O)
{
    extern __shared__ __align__(16) __half smem[];
    const uint32_t sb = smem_u32(smem);

    const int tid  = threadIdx.x;
    const int lane = tid & 31;
    const int warp = tid >> 5;
    const int wm   = warp >> 2;   // 0..1 : 64-row slab
    const int wn   = warp & 3;    // 0..3 : 32-col slab

    const int m0 = blockIdx.y * BM;
    const int n0 = blockIdx.x * BN;

    float acc[4][4][4];
#pragma unroll
    for (int i = 0; i < 4; i++)
#pragma unroll
        for (int j = 0; j < 4; j++)
#pragma unroll
            for (int k = 0; k < 4; k++) acc[i][j][k] = 0.f;

    // ---- hoisted per-thread addressing ----
    // loader plan (256 thr): A 128x64 halves = 1024 chunks -> 4/thr; B same.
    const int l_row = tid >> 3;          // 0..31
    const int l_col = (tid & 7) * 8;     // half offset

    uint32_t sa_off[4], sbo_off[4];      // smem STS targets (stage 0)
    const __half* ga[4];                 // gmem cursors (advance BK per issue)
    const __half* gb[4];
#pragma unroll
    for (int i = 0; i < 4; i++) {
        int row = l_row + i * 32;
        sa_off[i]  = sb + (uint32_t)(row * LDS_A + l_col) * 2;
        ga[i] = g_Ah + (size_t)(m0 + row) * K_TOTAL + l_col;
        sbo_off[i] = sb + B_BASE + (uint32_t)(row * LDS_B + l_col) * 2;
        gb[i] = g_Bh + (size_t)(n0 + row) * K_TOTAL + l_col;
    }

    // fragment LDSM base addresses (stage 0, ks 0)
    uint32_t a_off[4], b_off[2];
#pragma unroll
    for (int mi = 0; mi < 4; mi++)
        a_off[mi] = sb + (uint32_t)((wm * 64 + mi * 16 + (lane & 15)) * LDS_A +
                                    (lane >> 4) * 8) * 2;
    {
        int mm = lane >> 3;
#pragma unroll
        for (int bi = 0; bi < 2; bi++) {
            int nr = wn * 32 + bi * 16 + ((mm >> 1) << 3) + (lane & 7);
            b_off[bi] = sb + B_BASE +
                        (uint32_t)(nr * LDS_B + ((mm & 1) << 3)) * 2;
        }
    }

    auto issue_stage = [&](uint32_t offA, uint32_t offB) {
#pragma unroll
        for (int i = 0; i < 4; i++) {
            CP_ASYNC_16(sa_off[i] + offA, ga[i]);
            ga[i] += BK;
        }
#pragma unroll
        for (int i = 0; i < 4; i++) {
            CP_ASYNC_16(sbo_off[i] + offB, gb[i]);
            gb[i] += BK;
        }
    };

    auto compute = [&](uint32_t offA, uint32_t offB) {
#pragma unroll
        for (int ks = 0; ks < 4; ks++) {
            const uint32_t ko = (uint32_t)(ks * 32);
            uint32_t af[4][4];
            uint32_t bf[8];
#pragma unroll
            for (int mi = 0; mi < 4; mi++)
                LDSM4(af[mi][0], af[mi][1], af[mi][2], af[mi][3],
                      a_off[mi] + offA + ko);
            LDSM4(bf[0], bf[1], bf[2], bf[3], b_off[0] + offB + ko);
            LDSM4(bf[4], bf[5], bf[6], bf[7], b_off[1] + offB + ko);
#pragma unroll
            for (int mi = 0; mi < 4; mi++)
#pragma unroll
                for (int ni = 0; ni < 4; ni++)
                    HMMA(acc[mi][ni], af[mi], bf[ni * 2], bf[ni * 2 + 1]);
        }
    };

    // prologue: fill 2 of 3 stages
    issue_stage(0 * STRIDE_A, 0 * STRIDE_B); CP_COMMIT();
    issue_stage(1 * STRIDE_A, 1 * STRIDE_B); CP_COMMIT();

    int next = 2;  // next k-block to issue

    // body: wait(<=1 pending) -> stage CUR resident; sync; compute(CUR);
    // issue k-block `next` into stage NXT; commit (empty in tail).
#define BODY(CUR, NXT)                                                        \
    do {                                                                      \
        CP_WAIT(1);                                                           \
        __syncthreads();                                                      \
        compute((CUR) * STRIDE_A, (CUR) * STRIDE_B);                          \
        if (next < NT) {                                                      \
            issue_stage((NXT) * STRIDE_A, (NXT) * STRIDE_B);                  \
            next++;                                                           \
        }                                                                     \
        CP_COMMIT();                                                          \
    } while (0)

    // 64 iterations = 21 * 3 + 1; stage of iter 63 is 0.
#pragma unroll 1
    for (int tu = 0; tu < NT / 3; tu++) {   // 21 unrolled triples (63 iters)
        BODY(0, 2);
        BODY(1, 0);
        BODY(2, 1);
    }
    BODY(0, 2);                             // iter 63 (issue guard is false)
#undef BODY

    // ---- epilogue: f16(acc) + f16(bias), store f32 (matches reference rounding) ----
#pragma unroll
    for (int mi = 0; mi < 4; mi++) {
#pragma unroll
        for (int ni = 0; ni < 4; ni++) {
            int col = n0 + wn * 32 + ni * 8 + (lane & 3) * 2;
            float2 bf2 = *reinterpret_cast<const float2*>(BIAS + col);
            __half2 b2 = __floats2half2_rn(bf2.x, bf2.y);
            int r0 = m0 + wm * 64 + mi * 16 + (lane >> 2);

            __half2 v0 = __floats2half2_rn(acc[mi][ni][0], acc[mi][ni][1]);
            __half2 v1 = __floats2half2_rn(acc[mi][ni][2], acc[mi][ni][3]);
            float2 o0 = __half22float2(__hadd2(v0, b2));
            float2 o1 = __half22float2(__hadd2(v1, b2));
            *reinterpret_cast<float2*>(O + (size_t)r0 * N_TOTAL + col) = o0;
            *reinterpret_cast<float2*>(O + (size_t)(r0 + 8) * N_TOTAL + col) = o1;
        }
    }
}

extern "C" void kernel_launch(void* const* d_in, const int* in_sizes, int n_in,
                              void* d_out, int out_size)
{
    const float* x    = (const float*)d_in[0];
    const void*  w    = (const void*)d_in[1];
    const float* s    = (const float*)d_in[2];
    const float* bias = (const float*)d_in[3];
    float*       out  = (float*)d_out;

    cudaFuncSetAttribute(wq8_gemm_kernel,
                         cudaFuncAttributeMaxDynamicSharedMemorySize, SMEM_BYTES);

    probe_weight_kernel<<<1, 32>>>((const int8_t*)w);
    convert_x_kernel<<<(int)((size_t)M_TOTAL * K_TOTAL / 8 / 256), 256>>>(
        (const float4*)x);
    dequant_w_kernel<<<(int)((size_t)N_TOTAL * K_TOTAL / 8 / 256), 256>>>(w, s);

    dim3 grid(N_TOTAL / BN, M_TOTAL / BM);  // 86 x 64
    wq8_gemm_kernel<<<grid, THREADS, SMEM_BYTES>>>(bias, out);
}